// round 2
// baseline (speedup 1.0000x reference)
#include <cuda_runtime.h>
#include <cstdint>
#include <cstddef>

#define NTOK   32768      // B*T = 8*4096
#define KDIM   1024       // contraction dim for all GEMMs
#define NSTEPS (KDIM/16)

// ---------------- scratch (device globals: allocation-free) ----------------
__device__ float g_ql [NTOK*1024];
__device__ float g_kvm[NTOK*2048];
__device__ float g_qm [NTOK*1024];
__device__ float g_kvl[NTOK*2048];
__device__ float g_al [NTOK*1024];
__device__ float g_am [NTOK*1024];

// ---------------- helpers ----------------
__device__ __forceinline__ unsigned smem_u32(const void* p) {
    unsigned r;
    asm("{ .reg .u64 t; cvta.to.shared.u64 t, %1; cvt.u32.u64 %0, t; }"
        : "=r"(r) : "l"(p));
    return r;
}
__device__ __forceinline__ void cp_async16(unsigned s, const void* g) {
    asm volatile("cp.async.ca.shared.global [%0], [%1], 16;" :: "r"(s), "l"(g));
}
__device__ __forceinline__ void cp_commit() {
    asm volatile("cp.async.commit_group;");
}
template<int N>
__device__ __forceinline__ void cp_wait() {
    asm volatile("cp.async.wait_group %0;" :: "n"(N));
}
__device__ __forceinline__ unsigned long long pack2(float x) {
    unsigned long long r;
    asm("mov.b64 %0, {%1, %1};" : "=l"(r) : "f"(x));
    return r;
}
__device__ __forceinline__ void ffma2(unsigned long long& d,
                                      unsigned long long a,
                                      unsigned long long b) {
    asm("fma.rn.f32x2 %0, %1, %2, %0;" : "+l"(d) : "l"(a), "l"(b));
}

// ---------------- fp32 SGEMM: C[M,N] = A[M,KDIM] @ B[KDIM,N] + bias (+res) --
// BM=128, BN=128, BK=16, 128 threads, per-thread 8(M) x 16(N) via f32x2.
template<bool RES>
__global__ __launch_bounds__(128, 2)
void sgemm128(const float* __restrict__ A, const float* __restrict__ B,
              const float* __restrict__ bias, const float* __restrict__ res,
              float* __restrict__ C, int N)
{
    __shared__ float As[2][128*16];
    __shared__ float Bs[2][16*128];

    const int tid = threadIdx.x;
    const int tx  = tid & 7;    // N-group (16 cols each)
    const int ty  = tid >> 3;   // M-group (8 rows each)
    const int bm  = blockIdx.y * 128;
    const int bn  = blockIdx.x * 128;

    const unsigned sA = smem_u32(&As[0][0]);
    const unsigned sB = smem_u32(&Bs[0][0]);

    // prefetch one K-tile (16 deep) into buffer `buf`
    auto prefetch = [&](int k0, int buf) {
        unsigned sa = sA + (unsigned)buf * (128*16*4);
        unsigned sb = sB + (unsigned)buf * (16*128*4);
        #pragma unroll
        for (int i = 0; i < 4; i++) {
            int q = tid + i*128;            // 512 chunks of A tile
            int m = q >> 2, c = q & 3;
            const float* g = A + (size_t)(bm + m) * KDIM + k0 + c*4;
            int cc = c ^ ((m >> 3) & 3);    // XOR swizzle -> conflict-free a reads
            cp_async16(sa + (unsigned)(m*16 + cc*4) * 4, g);
        }
        #pragma unroll
        for (int i = 0; i < 4; i++) {
            int q = tid + i*128;            // 512 chunks of B tile
            int k = q >> 5, c = q & 31;
            const float* g = B + (size_t)(k0 + k) * N + bn + c*4;
            int sg = (c & 3) * 8 + (c >> 2); // chunk permutation -> conflict-free b reads
            cp_async16(sb + (unsigned)(k*128 + sg*4) * 4, g);
        }
        cp_commit();
    };

    unsigned long long acc[8][8];
    #pragma unroll
    for (int i = 0; i < 8; i++)
        #pragma unroll
        for (int p = 0; p < 8; p++) acc[i][p] = 0ull;

    prefetch(0, 0);

    for (int s = 0; s < NSTEPS; ++s) {
        if (s + 1 < NSTEPS) { prefetch((s+1)*16, (s+1) & 1); cp_wait<1>(); }
        else                { cp_wait<0>(); }
        __syncthreads();

        const float* as = &As[s & 1][0];
        const float* bs = &Bs[s & 1][0];

        #pragma unroll
        for (int kk = 0; kk < 16; kk++) {
            unsigned long long b2[8];
            #pragma unroll
            for (int sub = 0; sub < 4; sub++) {
                const ulonglong2 v =
                    *(const ulonglong2*)(bs + kk*128 + (sub*8 + tx)*4);
                b2[sub*2]   = v.x;
                b2[sub*2+1] = v.y;
            }
            unsigned long long a2[8];
            const int sw = ((kk >> 2) ^ (ty & 3)) * 4 + (kk & 3);
            #pragma unroll
            for (int i = 0; i < 8; i++)
                a2[i] = pack2(as[(ty*8 + i)*16 + sw]);

            #pragma unroll
            for (int i = 0; i < 8; i++)
                #pragma unroll
                for (int p = 0; p < 8; p++)
                    ffma2(acc[i][p], a2[i], b2[p]);
        }
        __syncthreads();
    }

    // epilogue: bias (+ residual), vectorized stores
    float4 bv[4];
    #pragma unroll
    for (int sub = 0; sub < 4; sub++)
        bv[sub] = *(const float4*)(bias + bn + tx*16 + sub*4);

    #pragma unroll
    for (int i = 0; i < 8; i++) {
        const size_t r = (size_t)(bm + ty*8 + i);
        float*       cp = C + r * N + bn + tx*16;
        const float* rp = RES ? (res + r * N + bn + tx*16) : nullptr;
        #pragma unroll
        for (int sub = 0; sub < 4; sub++) {
            float2 lo = *(float2*)&acc[i][sub*2];
            float2 hi = *(float2*)&acc[i][sub*2 + 1];
            float4 o;
            o.x = lo.x + bv[sub].x;
            o.y = lo.y + bv[sub].y;
            o.z = hi.x + bv[sub].z;
            o.w = hi.y + bv[sub].w;
            if (RES) {
                float4 rv = *(const float4*)(rp + sub*4);
                o.x += rv.x; o.y += rv.y; o.z += rv.z; o.w += rv.w;
            }
            *(float4*)(cp + sub*4) = o;
        }
    }
}

// ---------------- per-token 8x8 cross-head attention ----------------
// modality 0: q = g_ql, kv = g_kvm -> g_al ; modality 1: q = g_qm, kv = g_kvl -> g_am
__global__ __launch_bounds__(256)
void attn_kernel()
{
    const int tok = blockIdx.x;
    const int tid = threadIdx.x;

    __shared__ float sq [2][1024];
    __shared__ float skv[2][8*264];   // padded row (264) to kill bank conflicts
    __shared__ float swt[2][8][8];

    // load q (256 float4 each) and kv (512 float4 each, padded rows)
    {
        const float4* q0 = (const float4*)(g_ql + (size_t)tok * 1024);
        const float4* q1 = (const float4*)(g_qm + (size_t)tok * 1024);
        ((float4*)sq[0])[tid] = q0[tid];
        ((float4*)sq[1])[tid] = q1[tid];

        const float4* kv0 = (const float4*)(g_kvm + (size_t)tok * 2048);
        const float4* kv1 = (const float4*)(g_kvl + (size_t)tok * 2048);
        #pragma unroll
        for (int i = 0; i < 2; i++) {
            int o = tid + i*256;          // float4 index
            int g = o >> 6;               // head row
            int c = o & 63;               // float4 within row
            *(float4*)&skv[0][g*264 + c*4] = kv0[o];
            *(float4*)&skv[1][g*264 + c*4] = kv1[o];
        }
    }
    __syncthreads();

    // scores: 128 (mod,h,g) pairs, 2 threads each (split K=128 in halves)
    {
        const int p = tid >> 1, half = tid & 1;
        const int mod = p >> 6, h = (p >> 3) & 7, g = p & 7;
        const float* q = &sq [mod][h*128 + half*64];
        const float* k = &skv[mod][g*264 + half*64];
        float s = 0.f;
        #pragma unroll
        for (int d = 0; d < 64; d++) s += q[d] * k[d];
        s += __shfl_xor_sync(0xffffffffu, s, 1);
        if (half == 0) swt[mod][h][g] = s * 0.08838834764831845f; // 1/sqrt(128)
    }
    __syncthreads();

    // softmax over g (16 rows total)
    if (tid < 16) {
        const int mod = tid >> 3, h = tid & 7;
        float mx = -1e30f;
        #pragma unroll
        for (int g = 0; g < 8; g++) mx = fmaxf(mx, swt[mod][h][g]);
        float e[8], sum = 0.f;
        #pragma unroll
        for (int g = 0; g < 8; g++) { e[g] = __expf(swt[mod][h][g] - mx); sum += e[g]; }
        const float inv = 1.0f / sum;
        #pragma unroll
        for (int g = 0; g < 8; g++) swt[mod][h][g] = e[g] * inv;
    }
    __syncthreads();

    // output: a[h][d] = sum_g w[h][g] * v[g][d]
    {
        const int mod = tid >> 7, h = (tid >> 4) & 7, db = (tid & 15) * 8;
        float4 a0 = {0,0,0,0}, a1 = {0,0,0,0};
        #pragma unroll
        for (int g = 0; g < 8; g++) {
            const float w = swt[mod][h][g];
            const float4 v0 = *(const float4*)&skv[mod][g*264 + 128 + db];
            const float4 v1 = *(const float4*)&skv[mod][g*264 + 128 + db + 4];
            a0.x += w*v0.x; a0.y += w*v0.y; a0.z += w*v0.z; a0.w += w*v0.w;
            a1.x += w*v1.x; a1.y += w*v1.y; a1.z += w*v1.z; a1.w += w*v1.w;
        }
        float* out = (mod == 0 ? g_al : g_am) + (size_t)tok * 1024 + h*128 + db;
        *(float4*)(out)     = a0;
        *(float4*)(out + 4) = a1;
    }
}

// ---------------- launch ----------------
extern "C" void kernel_launch(void* const* d_in, const int* in_sizes, int n_in,
                              void* d_out, int out_size)
{
    (void)in_sizes; (void)n_in; (void)out_size;
    const float* liquid = (const float*)d_in[0];
    const float* mamba  = (const float*)d_in[1];
    const float* Wlq  = (const float*)d_in[2];
    const float* blq  = (const float*)d_in[3];
    const float* Wmkv = (const float*)d_in[4];
    const float* bmkv = (const float*)d_in[5];
    const float* Wmq  = (const float*)d_in[6];
    const float* bmq  = (const float*)d_in[7];
    const float* Wlkv = (const float*)d_in[8];
    const float* blkv = (const float*)d_in[9];
    const float* Wlo  = (const float*)d_in[10];
    const float* blo  = (const float*)d_in[11];
    const float* Wmo  = (const float*)d_in[12];
    const float* bmo  = (const float*)d_in[13];

    float* out_l = (float*)d_out;
    float* out_m = out_l + (size_t)NTOK * 1024;

    float *ql, *kvm, *qm, *kvl, *al, *am;
    cudaGetSymbolAddress((void**)&ql,  g_ql);
    cudaGetSymbolAddress((void**)&kvm, g_kvm);
    cudaGetSymbolAddress((void**)&qm,  g_qm);
    cudaGetSymbolAddress((void**)&kvl, g_kvl);
    cudaGetSymbolAddress((void**)&al,  g_al);
    cudaGetSymbolAddress((void**)&am,  g_am);

    const dim3 blk(128);
    const dim3 g1024(1024/128, NTOK/128);
    const dim3 g2048(2048/128, NTOK/128);

    // stage 1: projections
    sgemm128<false><<<g1024, blk>>>(liquid, Wlq,  blq,  nullptr, ql,  1024);
    sgemm128<false><<<g2048, blk>>>(mamba,  Wmkv, bmkv, nullptr, kvm, 2048);
    sgemm128<false><<<g1024, blk>>>(mamba,  Wmq,  bmq,  nullptr, qm,  1024);
    sgemm128<false><<<g2048, blk>>>(liquid, Wlkv, blkv, nullptr, kvl, 2048);

    // stage 2: per-token 8x8 attention (both modalities)
    attn_kernel<<<NTOK, 256>>>();

    // stage 3: output projections + residual
    sgemm128<true><<<g1024, blk>>>(al, Wlo, blo, liquid, out_l, 1024);
    sgemm128<true><<<g1024, blk>>>(am, Wmo, bmo, mamba,  out_m, 1024);
}

// round 4
// speedup vs baseline: 1.8810x; 1.8810x over previous
#include <cuda_runtime.h>
#include <cuda_bf16.h>
#include <cstdint>
#include <cstddef>

#define NTOK   32768      // B*T
#define KDIM   1024
#define BM     128
#define BN     128
#define BKB    64         // K elements per stage
#define NITER  (KDIM/BKB) // 16
#define NSTAGE 3

// per-stage smem layout (bytes): Ahi 16K | Alo 16K | Bhi 16K | Blo 16K
#define A_BYTES   (BM*128)
#define ST_BYTES  (4*A_BYTES)            // 65536
#define DSMEM_BYTES (NSTAGE*ST_BYTES)    // 196608

// ---------------- scratch (device globals) ----------------
__device__ float g_ql [NTOK*1024];
__device__ float g_kvm[(size_t)NTOK*2048];
__device__ float g_qm [NTOK*1024];
__device__ float g_kvl[(size_t)NTOK*2048];

__device__ __nv_bfloat16 g_lhi[NTOK*1024], g_llo[NTOK*1024];
__device__ __nv_bfloat16 g_mhi[NTOK*1024], g_mlo[NTOK*1024];
__device__ __nv_bfloat16 g_alhi[NTOK*1024], g_allo[NTOK*1024];
__device__ __nv_bfloat16 g_amhi[NTOK*1024], g_amlo[NTOK*1024];

__device__ __nv_bfloat16 g_wlq_h [1024*1024], g_wlq_l [1024*1024];
__device__ __nv_bfloat16 g_wmkv_h[2048*1024], g_wmkv_l[2048*1024];
__device__ __nv_bfloat16 g_wmq_h [1024*1024], g_wmq_l [1024*1024];
__device__ __nv_bfloat16 g_wlkv_h[2048*1024], g_wlkv_l[2048*1024];
__device__ __nv_bfloat16 g_wlo_h [1024*1024], g_wlo_l [1024*1024];
__device__ __nv_bfloat16 g_wmo_h [1024*1024], g_wmo_l [1024*1024];

// ---------------- PTX helpers ----------------
__device__ __forceinline__ unsigned smem_u32(const void* p) {
    unsigned r;
    asm("{ .reg .u64 t; cvta.to.shared.u64 t, %1; cvt.u32.u64 %0, t; }" : "=r"(r) : "l"(p));
    return r;
}
__device__ __forceinline__ void cp_async16(unsigned s, const void* g) {
    asm volatile("cp.async.ca.shared.global [%0], [%1], 16;" :: "r"(s), "l"(g));
}
__device__ __forceinline__ void cp_commit() { asm volatile("cp.async.commit_group;"); }
template<int N>
__device__ __forceinline__ void cp_wait() { asm volatile("cp.async.wait_group %0;" :: "n"(N)); }

__device__ __forceinline__ void ldsm_x4(uint32_t* r, unsigned addr) {
    asm volatile("ldmatrix.sync.aligned.m8n8.x4.shared.b16 {%0,%1,%2,%3}, [%4];"
        : "=r"(r[0]), "=r"(r[1]), "=r"(r[2]), "=r"(r[3]) : "r"(addr));
}
__device__ __forceinline__ void mma_bf16(float* d, const uint32_t* a, uint32_t b0, uint32_t b1) {
    asm volatile(
        "mma.sync.aligned.m16n8k16.row.col.f32.bf16.bf16.f32 "
        "{%0,%1,%2,%3}, {%4,%5,%6,%7}, {%8,%9}, {%0,%1,%2,%3};"
        : "+f"(d[0]), "+f"(d[1]), "+f"(d[2]), "+f"(d[3])
        : "r"(a[0]), "r"(a[1]), "r"(a[2]), "r"(a[3]), "r"(b0), "r"(b1));
}
__device__ __forceinline__ void split2(float v, __nv_bfloat16& h, __nv_bfloat16& l) {
    h = __float2bfloat16(v);
    l = __float2bfloat16(v - __bfloat162float(h));
}

// ---------------- split-bf16 MMA GEMM ----------------
// C[M,N](fp32) = (Ahi+Alo)[M,K] @ (Bhi+Blo)[N,K]^T + bias (+res). K=1024, M=32768.
template<bool RES>
__global__ __launch_bounds__(256, 1)
void gemm_mma(const __nv_bfloat16* __restrict__ Ahi, const __nv_bfloat16* __restrict__ Alo,
              const __nv_bfloat16* __restrict__ Bhi, const __nv_bfloat16* __restrict__ Blo,
              const float* __restrict__ bias, const float* __restrict__ res,
              float* __restrict__ C, int N, int gn)
{
    extern __shared__ char dsm[];
    const int tid = threadIdx.x;
    const int l   = tid & 31;
    const int w   = tid >> 5;
    const int wm  = w >> 2;   // 0..1
    const int wn  = w & 3;    // 0..3

    // GROUP_M=16 rasterization (gm = 256)
    const int gid   = blockIdx.x;
    const int width = 16 * gn;
    const int group = gid / width;
    const int inner = gid - group * width;
    const int m0 = (group * 16 + (inner & 15)) * BM;
    const int n0 = (inner >> 4) * BN;

    const unsigned sbase = smem_u32(dsm);

    // per-thread ldmatrix addressing constants
    const int rowA = wm * 64 + (l & 15);
    const int cA   = l >> 4;
    const int xA   = rowA & 7;
    const int rowB = wn * 32 + ((l >> 3) & 1) * 8 + (l & 7);
    const int cB   = l >> 4;
    const int xB   = rowB & 7;

    float acc[4][4][4];
    #pragma unroll
    for (int mi = 0; mi < 4; mi++)
        #pragma unroll
        for (int ni = 0; ni < 4; ni++)
            #pragma unroll
            for (int e = 0; e < 4; e++) acc[mi][ni][e] = 0.f;

    auto prefetch = [&](int chunk, int buf) {
        const int k0 = chunk * BKB;
        const unsigned st = sbase + (unsigned)buf * ST_BYTES;
        #pragma unroll
        for (int i = 0; i < 4; i++) {
            const int q = tid + i * 256;
            const int r = q >> 3, c = q & 7;
            const unsigned rel = (unsigned)(r * 128 + ((c ^ (r & 7)) << 4));
            const size_t ga = (size_t)(m0 + r) * KDIM + k0 + c * 8;
            const size_t gb = (size_t)(n0 + r) * KDIM + k0 + c * 8;
            cp_async16(st              + rel, Ahi + ga);
            cp_async16(st +   A_BYTES  + rel, Alo + ga);
            cp_async16(st + 2*A_BYTES  + rel, Bhi + gb);
            cp_async16(st + 3*A_BYTES  + rel, Blo + gb);
        }
        cp_commit();
    };

    prefetch(0, 0);
    prefetch(1, 1);
    prefetch(2, 2);

    for (int s = 0; s < NITER; ++s) {
        if (s <= NITER - 3)      cp_wait<2>();
        else if (s == NITER - 2) cp_wait<1>();
        else                     cp_wait<0>();
        __syncthreads();

        const unsigned st   = sbase + (unsigned)(s % 3) * ST_BYTES;
        const unsigned sAhi = st;
        const unsigned sAlo = st +   A_BYTES;
        const unsigned sBhi = st + 2*A_BYTES;
        const unsigned sBlo = st + 3*A_BYTES;

        #pragma unroll
        for (int ks = 0; ks < 4; ks++) {
            uint32_t ah[4][4], al[4][4], bh[2][4], bl[2][4];
            const unsigned ka = (unsigned)(((ks*2 + cA) ^ xA) << 4);
            const unsigned kb = (unsigned)(((ks*2 + cB) ^ xB) << 4);
            #pragma unroll
            for (int mi = 0; mi < 4; mi++) {
                const unsigned o = (unsigned)(rowA*128 + mi*2048) + ka;
                ldsm_x4(ah[mi], sAhi + o);
                ldsm_x4(al[mi], sAlo + o);
            }
            #pragma unroll
            for (int bj = 0; bj < 2; bj++) {
                const unsigned o = (unsigned)(rowB*128 + bj*2048) + kb;
                ldsm_x4(bh[bj], sBhi + o);
                ldsm_x4(bl[bj], sBlo + o);
            }
            #pragma unroll
            for (int mi = 0; mi < 4; mi++)
                #pragma unroll
                for (int ni = 0; ni < 4; ni++) {
                    const int bj = ni >> 1, sel = ni & 1;
                    mma_bf16(acc[mi][ni], ah[mi], bh[bj][sel], bh[bj][sel+2]);
                    mma_bf16(acc[mi][ni], ah[mi], bl[bj][sel], bl[bj][sel+2]);
                    mma_bf16(acc[mi][ni], al[mi], bh[bj][sel], bh[bj][sel+2]);
                }
        }
        __syncthreads();
        if (s + 3 < NITER) prefetch(s + 3, (s + 3) % 3);
    }

    // epilogue
    const int tr = l >> 2;
    const int tc = (l & 3) * 2;
    #pragma unroll
    for (int ni = 0; ni < 4; ni++) {
        const int col = n0 + wn*32 + ni*8 + tc;
        const float2 bv = *(const float2*)(bias + col);
        #pragma unroll
        for (int mi = 0; mi < 4; mi++) {
            const int row = m0 + wm*64 + mi*16 + tr;
            float2 o0, o1;
            o0.x = acc[mi][ni][0] + bv.x;  o0.y = acc[mi][ni][1] + bv.y;
            o1.x = acc[mi][ni][2] + bv.x;  o1.y = acc[mi][ni][3] + bv.y;
            if (RES) {
                const float2 r0 = *(const float2*)(res + (size_t)row * N + col);
                const float2 r1 = *(const float2*)(res + (size_t)(row+8) * N + col);
                o0.x += r0.x; o0.y += r0.y;
                o1.x += r1.x; o1.y += r1.y;
            }
            *(float2*)(C + (size_t)row     * N + col) = o0;
            *(float2*)(C + (size_t)(row+8) * N + col) = o1;
        }
    }
}

// ---------------- activation fp32 -> bf16 hi/lo split ----------------
__global__ __launch_bounds__(256)
void split_act(const float4* __restrict__ x, uint2* __restrict__ hi, uint2* __restrict__ lo)
{
    const int i = blockIdx.x * 256 + threadIdx.x;
    const float4 v = x[i];
    __nv_bfloat16 hb[4], lb[4];
    split2(v.x, hb[0], lb[0]);
    split2(v.y, hb[1], lb[1]);
    split2(v.z, hb[2], lb[2]);
    split2(v.w, hb[3], lb[3]);
    hi[i] = *(uint2*)hb;
    lo[i] = *(uint2*)lb;
}

// ---------------- weight transpose + split: W[K,N] -> T[N,K] hi/lo ----------------
__global__ __launch_bounds__(256)
void transpose_split(const float* __restrict__ W, __nv_bfloat16* __restrict__ Th,
                     __nv_bfloat16* __restrict__ Tl, int N)
{
    __shared__ float t[32][33];
    const int tx = threadIdx.x & 31, ty = threadIdx.x >> 5;
    const int bx = blockIdx.x * 32;   // N offset
    const int by = blockIdx.y * 32;   // K offset
    #pragma unroll
    for (int i = 0; i < 32; i += 8)
        t[ty + i][tx] = W[(size_t)(by + ty + i) * N + bx + tx];
    __syncthreads();
    #pragma unroll
    for (int i = 0; i < 32; i += 8) {
        const float v = t[tx][ty + i];
        const size_t o = (size_t)(bx + ty + i) * KDIM + by + tx;
        __nv_bfloat16 h, l;
        split2(v, h, l);
        Th[o] = h;
        Tl[o] = l;
    }
}

// ---------------- per-token 8x8 cross-head attention ----------------
__global__ __launch_bounds__(256)
void attn_kernel()
{
    const int tok = blockIdx.x;
    const int tid = threadIdx.x;

    __shared__ float sq [2][1024];
    __shared__ float skv[2][8*264];
    __shared__ float swt[2][8][8];

    {
        const float4* q0 = (const float4*)(g_ql + (size_t)tok * 1024);
        const float4* q1 = (const float4*)(g_qm + (size_t)tok * 1024);
        ((float4*)sq[0])[tid] = q0[tid];
        ((float4*)sq[1])[tid] = q1[tid];

        const float4* kv0 = (const float4*)(g_kvm + (size_t)tok * 2048);
        const float4* kv1 = (const float4*)(g_kvl + (size_t)tok * 2048);
        #pragma unroll
        for (int i = 0; i < 2; i++) {
            int o = tid + i*256;
            int g = o >> 6;
            int c = o & 63;
            *(float4*)&skv[0][g*264 + c*4] = kv0[o];
            *(float4*)&skv[1][g*264 + c*4] = kv1[o];
        }
    }
    __syncthreads();

    {
        const int p = tid >> 1, half = tid & 1;
        const int mod = p >> 6, h = (p >> 3) & 7, g = p & 7;
        const float* q = &sq [mod][h*128 + half*64];
        const float* k = &skv[mod][g*264 + half*64];
        float s = 0.f;
        #pragma unroll
        for (int d = 0; d < 64; d++) s += q[d] * k[d];
        s += __shfl_xor_sync(0xffffffffu, s, 1);
        if (half == 0) swt[mod][h][g] = s * 0.08838834764831845f; // 1/sqrt(128)
    }
    __syncthreads();

    if (tid < 16) {
        const int mod = tid >> 3, h = tid & 7;
        float mx = -1e30f;
        #pragma unroll
        for (int g = 0; g < 8; g++) mx = fmaxf(mx, swt[mod][h][g]);
        float e[8], sum = 0.f;
        #pragma unroll
        for (int g = 0; g < 8; g++) { e[g] = __expf(swt[mod][h][g] - mx); sum += e[g]; }
        const float inv = 1.0f / sum;
        #pragma unroll
        for (int g = 0; g < 8; g++) swt[mod][h][g] = e[g] * inv;
    }
    __syncthreads();

    {
        const int mod = tid >> 7, h = (tid >> 4) & 7, db = (tid & 15) * 8;
        float o[8] = {0,0,0,0,0,0,0,0};
        #pragma unroll
        for (int g = 0; g < 8; g++) {
            const float w = swt[mod][h][g];
            const float4 v0 = *(const float4*)&skv[mod][g*264 + 128 + db];
            const float4 v1 = *(const float4*)&skv[mod][g*264 + 128 + db + 4];
            o[0] += w*v0.x; o[1] += w*v0.y; o[2] += w*v0.z; o[3] += w*v0.w;
            o[4] += w*v1.x; o[5] += w*v1.y; o[6] += w*v1.z; o[7] += w*v1.w;
        }
        __nv_bfloat16 hb[8], lb[8];
        #pragma unroll
        for (int i = 0; i < 8; i++) split2(o[i], hb[i], lb[i]);
        const size_t off = (size_t)tok * 1024 + h*128 + db;
        __nv_bfloat16* ph = (mod == 0 ? g_alhi : g_amhi) + off;
        __nv_bfloat16* pl = (mod == 0 ? g_allo : g_amlo) + off;
        *(uint4*)ph = *(uint4*)hb;
        *(uint4*)pl = *(uint4*)lb;
    }
}

// ---------------- launch ----------------
extern "C" void kernel_launch(void* const* d_in, const int* in_sizes, int n_in,
                              void* d_out, int out_size)
{
    (void)in_sizes; (void)n_in; (void)out_size;
    const float* liquid = (const float*)d_in[0];
    const float* mamba  = (const float*)d_in[1];
    const float* Wlq  = (const float*)d_in[2];
    const float* blq  = (const float*)d_in[3];
    const float* Wmkv = (const float*)d_in[4];
    const float* bmkv = (const float*)d_in[5];
    const float* Wmq  = (const float*)d_in[6];
    const float* bmq  = (const float*)d_in[7];
    const float* Wlkv = (const float*)d_in[8];
    const float* blkv = (const float*)d_in[9];
    const float* Wlo  = (const float*)d_in[10];
    const float* blo  = (const float*)d_in[11];
    const float* Wmo  = (const float*)d_in[12];
    const float* bmo  = (const float*)d_in[13];

    float* out_l = (float*)d_out;
    float* out_m = out_l + (size_t)NTOK * 1024;

    #define SYM(p, s) void* p; cudaGetSymbolAddress(&p, s)
    SYM(ql, g_ql);  SYM(kvm, g_kvm); SYM(qm, g_qm);  SYM(kvl, g_kvl);
    SYM(lhi, g_lhi); SYM(llo, g_llo); SYM(mhi, g_mhi); SYM(mlo, g_mlo);
    SYM(alhi, g_alhi); SYM(allo, g_allo); SYM(amhi, g_amhi); SYM(amlo, g_amlo);
    SYM(wlq_h, g_wlq_h);   SYM(wlq_l, g_wlq_l);
    SYM(wmkv_h, g_wmkv_h); SYM(wmkv_l, g_wmkv_l);
    SYM(wmq_h, g_wmq_h);   SYM(wmq_l, g_wmq_l);
    SYM(wlkv_h, g_wlkv_h); SYM(wlkv_l, g_wlkv_l);
    SYM(wlo_h, g_wlo_h);   SYM(wlo_l, g_wlo_l);
    SYM(wmo_h, g_wmo_h);   SYM(wmo_l, g_wmo_l);
    #undef SYM

    cudaFuncSetAttribute(gemm_mma<false>, cudaFuncAttributeMaxDynamicSharedMemorySize, DSMEM_BYTES);
    cudaFuncSetAttribute(gemm_mma<true>,  cudaFuncAttributeMaxDynamicSharedMemorySize, DSMEM_BYTES);

    // stage 0: splits + weight transposes
    split_act<<<NTOK*1024/1024, 256>>>((const float4*)liquid, (uint2*)lhi, (uint2*)llo);
    split_act<<<NTOK*1024/1024, 256>>>((const float4*)mamba,  (uint2*)mhi, (uint2*)mlo);
    transpose_split<<<dim3(1024/32, 32), 256>>>(Wlq,  (__nv_bfloat16*)wlq_h,  (__nv_bfloat16*)wlq_l,  1024);
    transpose_split<<<dim3(2048/32, 32), 256>>>(Wmkv, (__nv_bfloat16*)wmkv_h, (__nv_bfloat16*)wmkv_l, 2048);
    transpose_split<<<dim3(1024/32, 32), 256>>>(Wmq,  (__nv_bfloat16*)wmq_h,  (__nv_bfloat16*)wmq_l,  1024);
    transpose_split<<<dim3(2048/32, 32), 256>>>(Wlkv, (__nv_bfloat16*)wlkv_h, (__nv_bfloat16*)wlkv_l, 2048);
    transpose_split<<<dim3(1024/32, 32), 256>>>(Wlo,  (__nv_bfloat16*)wlo_h,  (__nv_bfloat16*)wlo_l,  1024);
    transpose_split<<<dim3(1024/32, 32), 256>>>(Wmo,  (__nv_bfloat16*)wmo_h,  (__nv_bfloat16*)wmo_l,  1024);

    // stage 1: projections (tensor cores via mma.sync)
    const int gm = NTOK / BM;  // 256
    gemm_mma<false><<<gm * (1024/BN), 256, DSMEM_BYTES>>>(
        (const __nv_bfloat16*)lhi, (const __nv_bfloat16*)llo,
        (const __nv_bfloat16*)wlq_h, (const __nv_bfloat16*)wlq_l,
        blq, nullptr, (float*)ql, 1024, 1024/BN);
    gemm_mma<false><<<gm * (2048/BN), 256, DSMEM_BYTES>>>(
        (const __nv_bfloat16*)mhi, (const __nv_bfloat16*)mlo,
        (const __nv_bfloat16*)wmkv_h, (const __nv_bfloat16*)wmkv_l,
        bmkv, nullptr, (float*)kvm, 2048, 2048/BN);
    gemm_mma<false><<<gm * (1024/BN), 256, DSMEM_BYTES>>>(
        (const __nv_bfloat16*)mhi, (const __nv_bfloat16*)mlo,
        (const __nv_bfloat16*)wmq_h, (const __nv_bfloat16*)wmq_l,
        bmq, nullptr, (float*)qm, 1024, 1024/BN);
    gemm_mma<false><<<gm * (2048/BN), 256, DSMEM_BYTES>>>(
        (const __nv_bfloat16*)lhi, (const __nv_bfloat16*)llo,
        (const __nv_bfloat16*)wlkv_h, (const __nv_bfloat16*)wlkv_l,
        blkv, nullptr, (float*)kvl, 2048, 2048/BN);

    // stage 2: per-token attention (fp32 in, bf16 hi/lo out)
    attn_kernel<<<NTOK, 256>>>();

    // stage 3: output projections + residual
    gemm_mma<true><<<gm * (1024/BN), 256, DSMEM_BYTES>>>(
        (const __nv_bfloat16*)alhi, (const __nv_bfloat16*)allo,
        (const __nv_bfloat16*)wlo_h, (const __nv_bfloat16*)wlo_l,
        blo, liquid, out_l, 1024, 1024/BN);
    gemm_mma<true><<<gm * (1024/BN), 256, DSMEM_BYTES>>>(
        (const __nv_bfloat16*)amhi, (const __nv_bfloat16*)amlo,
        (const __nv_bfloat16*)wmo_h, (const __nv_bfloat16*)wmo_l,
        bmo, mamba, out_m, 1024, 1024/BN);
}

// round 5
// speedup vs baseline: 2.1181x; 1.1261x over previous
#include <cuda_runtime.h>
#include <cuda_bf16.h>
#include <cstdint>
#include <cstddef>

#define NTOK   32768      // B*T
#define KDIM   1024
#define BM     128
#define BN     256
#define BKB    64         // K elements per stage
#define NITER  (KDIM/BKB) // 16

// per-stage smem (bytes): Ahi 16K | Alo 16K | Bhi 32K | Blo 32K = 96K, 2 stages
#define A_BYTES   (BM*128)        // 16384
#define B_BYTES   (BN*128)        // 32768
#define ST_BYTES  (2*A_BYTES + 2*B_BYTES)   // 98304
#define DSMEM_BYTES (2*ST_BYTES)            // 196608
#define AHI_OFF 0
#define ALO_OFF (A_BYTES)
#define BHI_OFF (2*A_BYTES)
#define BLO_OFF (2*A_BYTES + B_BYTES)

// ---------------- scratch (device globals) ----------------
__device__ float g_ql [NTOK*1024];
__device__ float g_kvm[(size_t)NTOK*2048];
__device__ float g_qm [NTOK*1024];
__device__ float g_kvl[(size_t)NTOK*2048];

__device__ __nv_bfloat16 g_lhi[NTOK*1024], g_llo[NTOK*1024];
__device__ __nv_bfloat16 g_mhi[NTOK*1024], g_mlo[NTOK*1024];
__device__ __nv_bfloat16 g_alhi[NTOK*1024], g_allo[NTOK*1024];
__device__ __nv_bfloat16 g_amhi[NTOK*1024], g_amlo[NTOK*1024];

__device__ __nv_bfloat16 g_wlq_h [1024*1024], g_wlq_l [1024*1024];
__device__ __nv_bfloat16 g_wmkv_h[2048*1024], g_wmkv_l[2048*1024];
__device__ __nv_bfloat16 g_wmq_h [1024*1024], g_wmq_l [1024*1024];
__device__ __nv_bfloat16 g_wlkv_h[2048*1024], g_wlkv_l[2048*1024];
__device__ __nv_bfloat16 g_wlo_h [1024*1024], g_wlo_l [1024*1024];
__device__ __nv_bfloat16 g_wmo_h [1024*1024], g_wmo_l [1024*1024];

// ---------------- PTX helpers ----------------
__device__ __forceinline__ unsigned smem_u32(const void* p) {
    unsigned r;
    asm("{ .reg .u64 t; cvta.to.shared.u64 t, %1; cvt.u32.u64 %0, t; }" : "=r"(r) : "l"(p));
    return r;
}
__device__ __forceinline__ void cp_async16(unsigned s, const void* g) {
    asm volatile("cp.async.cg.shared.global [%0], [%1], 16;" :: "r"(s), "l"(g));
}
__device__ __forceinline__ void cp_commit() { asm volatile("cp.async.commit_group;"); }
template<int N>
__device__ __forceinline__ void cp_wait() { asm volatile("cp.async.wait_group %0;" :: "n"(N)); }

__device__ __forceinline__ void ldsm_x4(uint32_t* r, unsigned addr) {
    asm volatile("ldmatrix.sync.aligned.m8n8.x4.shared.b16 {%0,%1,%2,%3}, [%4];"
        : "=r"(r[0]), "=r"(r[1]), "=r"(r[2]), "=r"(r[3]) : "r"(addr));
}
__device__ __forceinline__ void mma_bf16(float* d, const uint32_t* a, uint32_t b0, uint32_t b1) {
    asm volatile(
        "mma.sync.aligned.m16n8k16.row.col.f32.bf16.bf16.f32 "
        "{%0,%1,%2,%3}, {%4,%5,%6,%7}, {%8,%9}, {%0,%1,%2,%3};"
        : "+f"(d[0]), "+f"(d[1]), "+f"(d[2]), "+f"(d[3])
        : "r"(a[0]), "r"(a[1]), "r"(a[2]), "r"(a[3]), "r"(b0), "r"(b1));
}
__device__ __forceinline__ void split2(float v, __nv_bfloat16& h, __nv_bfloat16& l) {
    h = __float2bfloat16(v);
    l = __float2bfloat16(v - __bfloat162float(h));
}

// ---------------- split-bf16 MMA GEMM ----------------
// C[M,N](fp32) = (Ahi+Alo)[M,K] @ (Bhi+Blo)[N,K]^T + bias (+res). K=1024, M=32768.
// 8 warps (2 x 2), warp tile 64 x 64. 2-stage cp.async pipeline.
template<bool RES>
__global__ __launch_bounds__(256, 1)
void gemm_mma(const __nv_bfloat16* __restrict__ Ahi, const __nv_bfloat16* __restrict__ Alo,
              const __nv_bfloat16* __restrict__ Bhi, const __nv_bfloat16* __restrict__ Blo,
              const float* __restrict__ bias, const float* __restrict__ res,
              float* __restrict__ C, int N, int gn)
{
    extern __shared__ char dsm[];
    const int tid = threadIdx.x;
    const int l   = tid & 31;
    const int w   = tid >> 5;
    const int wm  = w >> 2;   // 0..1  (64-row slab)
    const int wn  = w & 3;    // 0..3  (64-col slab)

    // GROUP_M=16 rasterization (gm = 256)
    const int gid   = blockIdx.x;
    const int width = 16 * gn;
    const int group = gid / width;
    const int inner = gid - group * width;
    const int m0 = (group * 16 + (inner & 15)) * BM;
    const int n0 = (inner >> 4) * BN;

    const unsigned sbase = smem_u32(dsm);

    // ldmatrix addressing
    const int rowA = wm * 64 + (l & 15);
    const int cA   = l >> 4;
    const int xA   = rowA & 7;
    const int rowB = wn * 64 + ((l >> 3) & 1) * 8 + (l & 7);
    const int cB   = l >> 4;
    const int xB   = rowB & 7;

    float acc[4][8][4];
    #pragma unroll
    for (int mi = 0; mi < 4; mi++)
        #pragma unroll
        for (int ni = 0; ni < 8; ni++)
            #pragma unroll
            for (int e = 0; e < 4; e++) acc[mi][ni][e] = 0.f;

    auto prefetch = [&](int chunk, int buf) {
        const int k0 = chunk * BKB;
        const unsigned st = sbase + (unsigned)buf * ST_BYTES;
        // A hi+lo: 1024 chunks each of 16B
        #pragma unroll
        for (int i = 0; i < 4; i++) {
            const int q = tid + i * 256;
            const int r = q >> 3, c = q & 7;
            const unsigned rel = (unsigned)(r * 128 + ((c ^ (r & 7)) << 4));
            const size_t ga = (size_t)(m0 + r) * KDIM + k0 + c * 8;
            cp_async16(st + AHI_OFF + rel, Ahi + ga);
            cp_async16(st + ALO_OFF + rel, Alo + ga);
        }
        // B hi+lo: 2048 chunks each
        #pragma unroll
        for (int i = 0; i < 8; i++) {
            const int q = tid + i * 256;
            const int r = q >> 3, c = q & 7;
            const unsigned rel = (unsigned)(r * 128 + ((c ^ (r & 7)) << 4));
            const size_t gb = (size_t)(n0 + r) * KDIM + k0 + c * 8;
            cp_async16(st + BHI_OFF + rel, Bhi + gb);
            cp_async16(st + BLO_OFF + rel, Blo + gb);
        }
        cp_commit();
    };

    prefetch(0, 0);
    prefetch(1, 1);

    for (int s = 0; s < NITER; ++s) {
        if (s < NITER - 1) cp_wait<1>(); else cp_wait<0>();
        __syncthreads();

        const unsigned st   = sbase + (unsigned)(s & 1) * ST_BYTES;
        const unsigned sAhi = st + AHI_OFF;
        const unsigned sAlo = st + ALO_OFF;
        const unsigned sBhi = st + BHI_OFF;
        const unsigned sBlo = st + BLO_OFF;

        #pragma unroll
        for (int ks = 0; ks < 4; ks++) {
            uint32_t ah[4][4], al[4][4], bh[4][4], bl[4][4];
            const unsigned ka = (unsigned)(((ks*2 + cA) ^ xA) << 4);
            const unsigned kb = (unsigned)(((ks*2 + cB) ^ xB) << 4);
            #pragma unroll
            for (int mi = 0; mi < 4; mi++) {
                const unsigned o = (unsigned)(rowA*128 + mi*2048) + ka;
                ldsm_x4(ah[mi], sAhi + o);
                ldsm_x4(al[mi], sAlo + o);
            }
            #pragma unroll
            for (int bj = 0; bj < 4; bj++) {
                const unsigned o = (unsigned)(rowB*128 + bj*2048) + kb;
                ldsm_x4(bh[bj], sBhi + o);
                ldsm_x4(bl[bj], sBlo + o);
            }
            #pragma unroll
            for (int mi = 0; mi < 4; mi++)
                #pragma unroll
                for (int ni = 0; ni < 8; ni++) {
                    const int bj = ni >> 1, sel = ni & 1;
                    mma_bf16(acc[mi][ni], ah[mi], bh[bj][sel], bh[bj][sel+2]);
                    mma_bf16(acc[mi][ni], ah[mi], bl[bj][sel], bl[bj][sel+2]);
                    mma_bf16(acc[mi][ni], al[mi], bh[bj][sel], bh[bj][sel+2]);
                }
        }
        __syncthreads();
        if (s + 2 < NITER) prefetch(s + 2, s & 1);
    }

    // epilogue
    const int tr = l >> 2;
    const int tc = (l & 3) * 2;
    #pragma unroll
    for (int ni = 0; ni < 8; ni++) {
        const int col = n0 + wn*64 + ni*8 + tc;
        const float2 bv = *(const float2*)(bias + col);
        #pragma unroll
        for (int mi = 0; mi < 4; mi++) {
            const int row = m0 + wm*64 + mi*16 + tr;
            float2 o0, o1;
            o0.x = acc[mi][ni][0] + bv.x;  o0.y = acc[mi][ni][1] + bv.y;
            o1.x = acc[mi][ni][2] + bv.x;  o1.y = acc[mi][ni][3] + bv.y;
            if (RES) {
                const float2 r0 = *(const float2*)(res + (size_t)row * N + col);
                const float2 r1 = *(const float2*)(res + (size_t)(row+8) * N + col);
                o0.x += r0.x; o0.y += r0.y;
                o1.x += r1.x; o1.y += r1.y;
            }
            *(float2*)(C + (size_t)row     * N + col) = o0;
            *(float2*)(C + (size_t)(row+8) * N + col) = o1;
        }
    }
}

// ---------------- activation fp32 -> bf16 hi/lo split ----------------
__global__ __launch_bounds__(256)
void split_act(const float4* __restrict__ x, uint2* __restrict__ hi, uint2* __restrict__ lo)
{
    const int i = blockIdx.x * 256 + threadIdx.x;
    const float4 v = x[i];
    __nv_bfloat16 hb[4], lb[4];
    split2(v.x, hb[0], lb[0]);
    split2(v.y, hb[1], lb[1]);
    split2(v.z, hb[2], lb[2]);
    split2(v.w, hb[3], lb[3]);
    hi[i] = *(uint2*)hb;
    lo[i] = *(uint2*)lb;
}

// ---------------- weight transpose + split: W[K,N] -> T[N,K] hi/lo ----------------
__global__ __launch_bounds__(256)
void transpose_split(const float* __restrict__ W, __nv_bfloat16* __restrict__ Th,
                     __nv_bfloat16* __restrict__ Tl, int N)
{
    __shared__ float t[32][33];
    const int tx = threadIdx.x & 31, ty = threadIdx.x >> 5;
    const int bx = blockIdx.x * 32;   // N offset
    const int by = blockIdx.y * 32;   // K offset
    #pragma unroll
    for (int i = 0; i < 32; i += 8)
        t[ty + i][tx] = W[(size_t)(by + ty + i) * N + bx + tx];
    __syncthreads();
    #pragma unroll
    for (int i = 0; i < 32; i += 8) {
        const float v = t[tx][ty + i];
        const size_t o = (size_t)(bx + ty + i) * KDIM + by + tx;
        __nv_bfloat16 h, l;
        split2(v, h, l);
        Th[o] = h;
        Tl[o] = l;
    }
}

// ---------------- per-token 8x8 cross-head attention ----------------
__global__ __launch_bounds__(256)
void attn_kernel()
{
    const int tok = blockIdx.x;
    const int tid = threadIdx.x;

    __shared__ float sq [2][1024];
    __shared__ float skv[2][8*264];
    __shared__ float swt[2][8][8];

    {
        const float4* q0 = (const float4*)(g_ql + (size_t)tok * 1024);
        const float4* q1 = (const float4*)(g_qm + (size_t)tok * 1024);
        ((float4*)sq[0])[tid] = q0[tid];
        ((float4*)sq[1])[tid] = q1[tid];

        const float4* kv0 = (const float4*)(g_kvm + (size_t)tok * 2048);
        const float4* kv1 = (const float4*)(g_kvl + (size_t)tok * 2048);
        #pragma unroll
        for (int i = 0; i < 2; i++) {
            int o = tid + i*256;
            int g = o >> 6;
            int c = o & 63;
            *(float4*)&skv[0][g*264 + c*4] = kv0[o];
            *(float4*)&skv[1][g*264 + c*4] = kv1[o];
        }
    }
    __syncthreads();

    {
        const int p = tid >> 1, half = tid & 1;
        const int mod = p >> 6, h = (p >> 3) & 7, g = p & 7;
        const float* q = &sq [mod][h*128 + half*64];
        const float* k = &skv[mod][g*264 + half*64];
        float s = 0.f;
        #pragma unroll
        for (int d = 0; d < 64; d++) s += q[d] * k[d];
        s += __shfl_xor_sync(0xffffffffu, s, 1);
        if (half == 0) swt[mod][h][g] = s * 0.08838834764831845f; // 1/sqrt(128)
    }
    __syncthreads();

    if (tid < 16) {
        const int mod = tid >> 3, h = tid & 7;
        float mx = -1e30f;
        #pragma unroll
        for (int g = 0; g < 8; g++) mx = fmaxf(mx, swt[mod][h][g]);
        float e[8], sum = 0.f;
        #pragma unroll
        for (int g = 0; g < 8; g++) { e[g] = __expf(swt[mod][h][g] - mx); sum += e[g]; }
        const float inv = 1.0f / sum;
        #pragma unroll
        for (int g = 0; g < 8; g++) swt[mod][h][g] = e[g] * inv;
    }
    __syncthreads();

    {
        const int mod = tid >> 7, h = (tid >> 4) & 7, db = (tid & 15) * 8;
        float o[8] = {0,0,0,0,0,0,0,0};
        #pragma unroll
        for (int g = 0; g < 8; g++) {
            const float w = swt[mod][h][g];
            const float4 v0 = *(const float4*)&skv[mod][g*264 + 128 + db];
            const float4 v1 = *(const float4*)&skv[mod][g*264 + 128 + db + 4];
            o[0] += w*v0.x; o[1] += w*v0.y; o[2] += w*v0.z; o[3] += w*v0.w;
            o[4] += w*v1.x; o[5] += w*v1.y; o[6] += w*v1.z; o[7] += w*v1.w;
        }
        __nv_bfloat16 hb[8], lb[8];
        #pragma unroll
        for (int i = 0; i < 8; i++) split2(o[i], hb[i], lb[i]);
        const size_t off = (size_t)tok * 1024 + h*128 + db;
        __nv_bfloat16* ph = (mod == 0 ? g_alhi : g_amhi) + off;
        __nv_bfloat16* pl = (mod == 0 ? g_allo : g_amlo) + off;
        *(uint4*)ph = *(uint4*)hb;
        *(uint4*)pl = *(uint4*)lb;
    }
}

// ---------------- launch ----------------
extern "C" void kernel_launch(void* const* d_in, const int* in_sizes, int n_in,
                              void* d_out, int out_size)
{
    (void)in_sizes; (void)n_in; (void)out_size;
    const float* liquid = (const float*)d_in[0];
    const float* mamba  = (const float*)d_in[1];
    const float* Wlq  = (const float*)d_in[2];
    const float* blq  = (const float*)d_in[3];
    const float* Wmkv = (const float*)d_in[4];
    const float* bmkv = (const float*)d_in[5];
    const float* Wmq  = (const float*)d_in[6];
    const float* bmq  = (const float*)d_in[7];
    const float* Wlkv = (const float*)d_in[8];
    const float* blkv = (const float*)d_in[9];
    const float* Wlo  = (const float*)d_in[10];
    const float* blo  = (const float*)d_in[11];
    const float* Wmo  = (const float*)d_in[12];
    const float* bmo  = (const float*)d_in[13];

    float* out_l = (float*)d_out;
    float* out_m = out_l + (size_t)NTOK * 1024;

    #define SYM(p, s) void* p; cudaGetSymbolAddress(&p, s)
    SYM(ql, g_ql);  SYM(kvm, g_kvm); SYM(qm, g_qm);  SYM(kvl, g_kvl);
    SYM(lhi, g_lhi); SYM(llo, g_llo); SYM(mhi, g_mhi); SYM(mlo, g_mlo);
    SYM(alhi, g_alhi); SYM(allo, g_allo); SYM(amhi, g_amhi); SYM(amlo, g_amlo);
    SYM(wlq_h, g_wlq_h);   SYM(wlq_l, g_wlq_l);
    SYM(wmkv_h, g_wmkv_h); SYM(wmkv_l, g_wmkv_l);
    SYM(wmq_h, g_wmq_h);   SYM(wmq_l, g_wmq_l);
    SYM(wlkv_h, g_wlkv_h); SYM(wlkv_l, g_wlkv_l);
    SYM(wlo_h, g_wlo_h);   SYM(wlo_l, g_wlo_l);
    SYM(wmo_h, g_wmo_h);   SYM(wmo_l, g_wmo_l);
    #undef SYM

    cudaFuncSetAttribute(gemm_mma<false>, cudaFuncAttributeMaxDynamicSharedMemorySize, DSMEM_BYTES);
    cudaFuncSetAttribute(gemm_mma<true>,  cudaFuncAttributeMaxDynamicSharedMemorySize, DSMEM_BYTES);

    // stage 0: splits + weight transposes
    split_act<<<NTOK*1024/1024, 256>>>((const float4*)liquid, (uint2*)lhi, (uint2*)llo);
    split_act<<<NTOK*1024/1024, 256>>>((const float4*)mamba,  (uint2*)mhi, (uint2*)mlo);
    transpose_split<<<dim3(1024/32, 32), 256>>>(Wlq,  (__nv_bfloat16*)wlq_h,  (__nv_bfloat16*)wlq_l,  1024);
    transpose_split<<<dim3(2048/32, 32), 256>>>(Wmkv, (__nv_bfloat16*)wmkv_h, (__nv_bfloat16*)wmkv_l, 2048);
    transpose_split<<<dim3(1024/32, 32), 256>>>(Wmq,  (__nv_bfloat16*)wmq_h,  (__nv_bfloat16*)wmq_l,  1024);
    transpose_split<<<dim3(2048/32, 32), 256>>>(Wlkv, (__nv_bfloat16*)wlkv_h, (__nv_bfloat16*)wlkv_l, 2048);
    transpose_split<<<dim3(1024/32, 32), 256>>>(Wlo,  (__nv_bfloat16*)wlo_h,  (__nv_bfloat16*)wlo_l,  1024);
    transpose_split<<<dim3(1024/32, 32), 256>>>(Wmo,  (__nv_bfloat16*)wmo_h,  (__nv_bfloat16*)wmo_l,  1024);

    // stage 1: projections (tensor cores via mma.sync)
    const int gm = NTOK / BM;  // 256
    gemm_mma<false><<<gm * (1024/BN), 256, DSMEM_BYTES>>>(
        (const __nv_bfloat16*)lhi, (const __nv_bfloat16*)llo,
        (const __nv_bfloat16*)wlq_h, (const __nv_bfloat16*)wlq_l,
        blq, nullptr, (float*)ql, 1024, 1024/BN);
    gemm_mma<false><<<gm * (2048/BN), 256, DSMEM_BYTES>>>(
        (const __nv_bfloat16*)mhi, (const __nv_bfloat16*)mlo,
        (const __nv_bfloat16*)wmkv_h, (const __nv_bfloat16*)wmkv_l,
        bmkv, nullptr, (float*)kvm, 2048, 2048/BN);
    gemm_mma<false><<<gm * (1024/BN), 256, DSMEM_BYTES>>>(
        (const __nv_bfloat16*)mhi, (const __nv_bfloat16*)mlo,
        (const __nv_bfloat16*)wmq_h, (const __nv_bfloat16*)wmq_l,
        bmq, nullptr, (float*)qm, 1024, 1024/BN);
    gemm_mma<false><<<gm * (2048/BN), 256, DSMEM_BYTES>>>(
        (const __nv_bfloat16*)lhi, (const __nv_bfloat16*)llo,
        (const __nv_bfloat16*)wlkv_h, (const __nv_bfloat16*)wlkv_l,
        blkv, nullptr, (float*)kvl, 2048, 2048/BN);

    // stage 2: per-token attention (fp32 in, bf16 hi/lo out)
    attn_kernel<<<NTOK, 256>>>();

    // stage 3: output projections + residual
    gemm_mma<true><<<gm * (1024/BN), 256, DSMEM_BYTES>>>(
        (const __nv_bfloat16*)alhi, (const __nv_bfloat16*)allo,
        (const __nv_bfloat16*)wlo_h, (const __nv_bfloat16*)wlo_l,
        blo, liquid, out_l, 1024, 1024/BN);
    gemm_mma<true><<<gm * (1024/BN), 256, DSMEM_BYTES>>>(
        (const __nv_bfloat16*)amhi, (const __nv_bfloat16*)amlo,
        (const __nv_bfloat16*)wmo_h, (const __nv_bfloat16*)wmo_l,
        bmo, mamba, out_m, 1024, 1024/BN);
}

// round 6
// speedup vs baseline: 5.2046x; 2.4572x over previous
#include <cuda_runtime.h>
#include <cuda_fp16.h>
#include <cstdint>
#include <cstddef>

#define NTOK   32768      // B*T
#define KDIM   1024
#define BM     128
#define BN     256
#define BKB    64         // K per stage
#define NITER  (KDIM/BKB) // 16
#define NSTAGE 4

// per-stage smem: A 16K + B 32K = 48K; 4 stages = 192K
#define A_BYTES   (BM*128)
#define B_BYTES   (BN*128)
#define ST_BYTES  (A_BYTES + B_BYTES)
#define DSMEM_BYTES (NSTAGE*ST_BYTES)

// ---------------- scratch (device globals) ----------------
__device__ __half g_l16[NTOK*1024], g_m16[NTOK*1024];          // fp16 activations
__device__ __half g_ql [NTOK*1024], g_qm [NTOK*1024];          // fp16 q
__device__ __half g_kvm[(size_t)NTOK*2048], g_kvl[(size_t)NTOK*2048]; // fp16 kv
__device__ __half g_al [NTOK*1024], g_am [NTOK*1024];          // fp16 attn out

__device__ __half g_wlq [1024*1024];
__device__ __half g_wmkv[2048*1024];
__device__ __half g_wmq [1024*1024];
__device__ __half g_wlkv[2048*1024];
__device__ __half g_wlo [1024*1024];
__device__ __half g_wmo [1024*1024];

// ---------------- PTX helpers ----------------
__device__ __forceinline__ unsigned smem_u32(const void* p) {
    unsigned r;
    asm("{ .reg .u64 t; cvta.to.shared.u64 t, %1; cvt.u32.u64 %0, t; }" : "=r"(r) : "l"(p));
    return r;
}
__device__ __forceinline__ void cp_async16(unsigned s, const void* g) {
    asm volatile("cp.async.cg.shared.global [%0], [%1], 16;" :: "r"(s), "l"(g));
}
__device__ __forceinline__ void cp_commit() { asm volatile("cp.async.commit_group;"); }
template<int N>
__device__ __forceinline__ void cp_wait() { asm volatile("cp.async.wait_group %0;" :: "n"(N)); }

__device__ __forceinline__ void ldsm_x4(uint32_t* r, unsigned addr) {
    asm volatile("ldmatrix.sync.aligned.m8n8.x4.shared.b16 {%0,%1,%2,%3}, [%4];"
        : "=r"(r[0]), "=r"(r[1]), "=r"(r[2]), "=r"(r[3]) : "r"(addr));
}
__device__ __forceinline__ void mma_f16(float* d, const uint32_t* a, uint32_t b0, uint32_t b1) {
    asm volatile(
        "mma.sync.aligned.m16n8k16.row.col.f32.f16.f16.f32 "
        "{%0,%1,%2,%3}, {%4,%5,%6,%7}, {%8,%9}, {%0,%1,%2,%3};"
        : "+f"(d[0]), "+f"(d[1]), "+f"(d[2]), "+f"(d[3])
        : "r"(a[0]), "r"(a[1]), "r"(a[2]), "r"(a[3]), "r"(b0), "r"(b1));
}

// ---------------- fp16 MMA GEMM ----------------
// acc(fp32) = A[M,K]fp16 @ B[N,K]fp16^T + bias.
// OUT_HALF: C fp16 [M,N].  else: C fp32 [M,N] += res.
// 8 warps (2x4), warp tile 64x64, 4-stage cp.async pipeline.
template<bool OUT_HALF>
__global__ __launch_bounds__(256, 1)
void gemm_f16(const __half* __restrict__ A, const __half* __restrict__ B,
              const float* __restrict__ bias, const float* __restrict__ res,
              void* __restrict__ Cout, int N, int gn)
{
    extern __shared__ char dsm[];
    const int tid = threadIdx.x;
    const int l   = tid & 31;
    const int w   = tid >> 5;
    const int wm  = w >> 2;   // 0..1
    const int wn  = w & 3;    // 0..3

    // GROUP_M=16 rasterization
    const int gid   = blockIdx.x;
    const int width = 16 * gn;
    const int group = gid / width;
    const int inner = gid - group * width;
    const int m0 = (group * 16 + (inner & 15)) * BM;
    const int n0 = (inner >> 4) * BN;

    const unsigned sbase = smem_u32(dsm);

    const int rowA = wm * 64 + (l & 15);
    const int cA   = l >> 4;
    const int xA   = rowA & 7;
    const int rowB = wn * 64 + ((l >> 3) & 1) * 8 + (l & 7);
    const int cB   = l >> 4;
    const int xB   = rowB & 7;

    float acc[4][8][4];
    #pragma unroll
    for (int mi = 0; mi < 4; mi++)
        #pragma unroll
        for (int ni = 0; ni < 8; ni++)
            #pragma unroll
            for (int e = 0; e < 4; e++) acc[mi][ni][e] = 0.f;

    auto prefetch = [&](int chunk, int buf) {
        const int k0 = chunk * BKB;
        const unsigned st = sbase + (unsigned)buf * ST_BYTES;
        #pragma unroll
        for (int i = 0; i < 4; i++) {             // A: 1024 16B-chunks
            const int q = tid + i * 256;
            const int r = q >> 3, c = q & 7;
            const unsigned rel = (unsigned)(r * 128 + ((c ^ (r & 7)) << 4));
            cp_async16(st + rel, A + (size_t)(m0 + r) * KDIM + k0 + c * 8);
        }
        #pragma unroll
        for (int i = 0; i < 8; i++) {             // B: 2048 16B-chunks
            const int q = tid + i * 256;
            const int r = q >> 3, c = q & 7;
            const unsigned rel = (unsigned)(r * 128 + ((c ^ (r & 7)) << 4));
            cp_async16(st + A_BYTES + rel, B + (size_t)(n0 + r) * KDIM + k0 + c * 8);
        }
        cp_commit();
    };

    prefetch(0, 0);
    prefetch(1, 1);
    prefetch(2, 2);

    for (int s = 0; s < NITER; ++s) {
        if (s <= NITER - 3)      cp_wait<2>();
        else if (s == NITER - 2) cp_wait<1>();
        else                     cp_wait<0>();
        __syncthreads();

        const unsigned st = sbase + (unsigned)(s & 3) * ST_BYTES;
        const unsigned sA = st;
        const unsigned sB = st + A_BYTES;

        #pragma unroll
        for (int ks = 0; ks < 4; ks++) {
            uint32_t a[4][4], b[4][4];
            const unsigned ka = (unsigned)(((ks*2 + cA) ^ xA) << 4);
            const unsigned kb = (unsigned)(((ks*2 + cB) ^ xB) << 4);
            #pragma unroll
            for (int mi = 0; mi < 4; mi++)
                ldsm_x4(a[mi], sA + (unsigned)(rowA*128 + mi*2048) + ka);
            #pragma unroll
            for (int bj = 0; bj < 4; bj++)
                ldsm_x4(b[bj], sB + (unsigned)(rowB*128 + bj*2048) + kb);
            #pragma unroll
            for (int mi = 0; mi < 4; mi++)
                #pragma unroll
                for (int ni = 0; ni < 8; ni++) {
                    const int bj = ni >> 1, sel = ni & 1;
                    mma_f16(acc[mi][ni], a[mi], b[bj][sel], b[bj][sel+2]);
                }
        }
        __syncthreads();
        if (s + 3 < NITER) prefetch(s + 3, (s + 3) & 3);
    }

    // epilogue
    const int tr = l >> 2;
    const int tc = (l & 3) * 2;
    #pragma unroll
    for (int ni = 0; ni < 8; ni++) {
        const int col = n0 + wn*64 + ni*8 + tc;
        const float2 bv = *(const float2*)(bias + col);
        #pragma unroll
        for (int mi = 0; mi < 4; mi++) {
            const int row = m0 + wm*64 + mi*16 + tr;
            float x0 = acc[mi][ni][0] + bv.x, y0 = acc[mi][ni][1] + bv.y;
            float x1 = acc[mi][ni][2] + bv.x, y1 = acc[mi][ni][3] + bv.y;
            if (OUT_HALF) {
                __half2* C = (__half2*)Cout;
                C[((size_t)row     * N + col) >> 1] = __floats2half2_rn(x0, y0);
                C[((size_t)(row+8) * N + col) >> 1] = __floats2half2_rn(x1, y1);
            } else {
                float* C = (float*)Cout;
                const float2 r0 = *(const float2*)(res + (size_t)row * N + col);
                const float2 r1 = *(const float2*)(res + (size_t)(row+8) * N + col);
                *(float2*)(C + (size_t)row     * N + col) = make_float2(x0 + r0.x, y0 + r0.y);
                *(float2*)(C + (size_t)(row+8) * N + col) = make_float2(x1 + r1.x, y1 + r1.y);
            }
        }
    }
}

// ---------------- activation fp32 -> fp16 ----------------
__global__ __launch_bounds__(256)
void cvt_act(const float4* __restrict__ x, uint2* __restrict__ o)
{
    const int i = blockIdx.x * 256 + threadIdx.x;
    const float4 v = x[i];
    __half2 a = __floats2half2_rn(v.x, v.y);
    __half2 b = __floats2half2_rn(v.z, v.w);
    o[i] = make_uint2(*(uint32_t*)&a, *(uint32_t*)&b);
}

// ---------------- weight transpose+convert: W[K,N] -> T[N,K] fp16 ----------------
__global__ __launch_bounds__(256)
void transpose_cvt(const float* __restrict__ W, __half* __restrict__ T, int N)
{
    __shared__ float t[32][33];
    const int tx = threadIdx.x & 31, ty = threadIdx.x >> 5;
    const int bx = blockIdx.x * 32;   // N offset
    const int by = blockIdx.y * 32;   // K offset
    #pragma unroll
    for (int i = 0; i < 32; i += 8)
        t[ty + i][tx] = W[(size_t)(by + ty + i) * N + bx + tx];
    __syncthreads();
    #pragma unroll
    for (int i = 0; i < 32; i += 8)
        T[(size_t)(bx + ty + i) * KDIM + by + tx] = __float2half(t[tx][ty + i]);
}

// ---------------- per-token 8x8 cross-head attention (fp16 in/out) ----------------
__global__ __launch_bounds__(256)
void attn_kernel()
{
    const int tok = blockIdx.x;
    const int tid = threadIdx.x;

    __shared__ __half sq [2][1024];
    __shared__ __half skv[2][8*264];   // 264-half row pitch (16B pad)
    __shared__ float  swt[2][8][8];

    {
        // q: 128 uint4 per modality
        const uint4* q0 = (const uint4*)(g_ql + (size_t)tok * 1024);
        const uint4* q1 = (const uint4*)(g_qm + (size_t)tok * 1024);
        if (tid < 128) ((uint4*)sq[0])[tid] = q0[tid];
        else           ((uint4*)sq[1])[tid - 128] = q1[tid - 128];

        // kv: 256 uint4 per modality
        const uint4* kv0 = (const uint4*)(g_kvm + (size_t)tok * 2048);
        const uint4* kv1 = (const uint4*)(g_kvl + (size_t)tok * 2048);
        #pragma unroll
        for (int i = 0; i < 2; i++) {
            int o = tid + i*256;       // 0..511
            int mod = o >> 8;
            int o8  = o & 255;         // uint4 index within modality
            int g = o8 >> 5;           // head
            int c = o8 & 31;           // uint4 within 256-half row
            uint4 v = mod ? kv1[o8] : kv0[o8];
            *(uint4*)&skv[mod][g*264 + c*8] = v;
        }
    }
    __syncthreads();

    {
        const int p = tid >> 1, half = tid & 1;
        const int mod = p >> 6, h = (p >> 3) & 7, g = p & 7;
        const __half2* q = (const __half2*)&sq [mod][h*128 + half*64];
        const __half2* k = (const __half2*)&skv[mod][g*264 + half*64];
        float s = 0.f;
        #pragma unroll
        for (int d = 0; d < 32; d++) {
            const float2 qf = __half22float2(q[d]);
            const float2 kf = __half22float2(k[d]);
            s += qf.x * kf.x + qf.y * kf.y;
        }
        s += __shfl_xor_sync(0xffffffffu, s, 1);
        if (half == 0) swt[mod][h][g] = s * 0.08838834764831845f; // 1/sqrt(128)
    }
    __syncthreads();

    if (tid < 16) {
        const int mod = tid >> 3, h = tid & 7;
        float mx = -1e30f;
        #pragma unroll
        for (int g = 0; g < 8; g++) mx = fmaxf(mx, swt[mod][h][g]);
        float e[8], sum = 0.f;
        #pragma unroll
        for (int g = 0; g < 8; g++) { e[g] = __expf(swt[mod][h][g] - mx); sum += e[g]; }
        const float inv = 1.0f / sum;
        #pragma unroll
        for (int g = 0; g < 8; g++) swt[mod][h][g] = e[g] * inv;
    }
    __syncthreads();

    {
        const int mod = tid >> 7, h = (tid >> 4) & 7, db = (tid & 15) * 8;
        float o[8] = {0,0,0,0,0,0,0,0};
        #pragma unroll
        for (int g = 0; g < 8; g++) {
            const float w = swt[mod][h][g];
            const __half2* v = (const __half2*)&skv[mod][g*264 + 128 + db];
            #pragma unroll
            for (int j = 0; j < 4; j++) {
                const float2 vf = __half22float2(v[j]);
                o[2*j]   += w * vf.x;
                o[2*j+1] += w * vf.y;
            }
        }
        __half hb[8];
        #pragma unroll
        for (int i = 0; i < 8; i++) hb[i] = __float2half(o[i]);
        __half* out = (mod == 0 ? g_al : g_am) + (size_t)tok * 1024 + h*128 + db;
        *(uint4*)out = *(uint4*)hb;
    }
}

// ---------------- launch ----------------
extern "C" void kernel_launch(void* const* d_in, const int* in_sizes, int n_in,
                              void* d_out, int out_size)
{
    (void)in_sizes; (void)n_in; (void)out_size;
    const float* liquid = (const float*)d_in[0];
    const float* mamba  = (const float*)d_in[1];
    const float* Wlq  = (const float*)d_in[2];
    const float* blq  = (const float*)d_in[3];
    const float* Wmkv = (const float*)d_in[4];
    const float* bmkv = (const float*)d_in[5];
    const float* Wmq  = (const float*)d_in[6];
    const float* bmq  = (const float*)d_in[7];
    const float* Wlkv = (const float*)d_in[8];
    const float* blkv = (const float*)d_in[9];
    const float* Wlo  = (const float*)d_in[10];
    const float* blo  = (const float*)d_in[11];
    const float* Wmo  = (const float*)d_in[12];
    const float* bmo  = (const float*)d_in[13];

    float* out_l = (float*)d_out;
    float* out_m = out_l + (size_t)NTOK * 1024;

    #define SYM(p, s) void* p; cudaGetSymbolAddress(&p, s)
    SYM(l16, g_l16); SYM(m16, g_m16);
    SYM(ql, g_ql);   SYM(qm, g_qm);
    SYM(kvm, g_kvm); SYM(kvl, g_kvl);
    SYM(al, g_al);   SYM(am, g_am);
    SYM(wlq, g_wlq); SYM(wmkv, g_wmkv); SYM(wmq, g_wmq);
    SYM(wlkv, g_wlkv); SYM(wlo, g_wlo); SYM(wmo, g_wmo);
    #undef SYM

    cudaFuncSetAttribute(gemm_f16<true>,  cudaFuncAttributeMaxDynamicSharedMemorySize, DSMEM_BYTES);
    cudaFuncSetAttribute(gemm_f16<false>, cudaFuncAttributeMaxDynamicSharedMemorySize, DSMEM_BYTES);

    // stage 0: convert activations + transpose/convert weights
    cvt_act<<<NTOK*1024/1024, 256>>>((const float4*)liquid, (uint2*)l16);
    cvt_act<<<NTOK*1024/1024, 256>>>((const float4*)mamba,  (uint2*)m16);
    transpose_cvt<<<dim3(1024/32, 32), 256>>>(Wlq,  (__half*)wlq,  1024);
    transpose_cvt<<<dim3(2048/32, 32), 256>>>(Wmkv, (__half*)wmkv, 2048);
    transpose_cvt<<<dim3(1024/32, 32), 256>>>(Wmq,  (__half*)wmq,  1024);
    transpose_cvt<<<dim3(2048/32, 32), 256>>>(Wlkv, (__half*)wlkv, 2048);
    transpose_cvt<<<dim3(1024/32, 32), 256>>>(Wlo,  (__half*)wlo,  1024);
    transpose_cvt<<<dim3(1024/32, 32), 256>>>(Wmo,  (__half*)wmo,  1024);

    // stage 1: projections -> fp16
    const int gm = NTOK / BM;  // 256
    gemm_f16<true><<<gm * (1024/BN), 256, DSMEM_BYTES>>>(
        (const __half*)l16, (const __half*)wlq, blq, nullptr, ql, 1024, 1024/BN);
    gemm_f16<true><<<gm * (2048/BN), 256, DSMEM_BYTES>>>(
        (const __half*)m16, (const __half*)wmkv, bmkv, nullptr, kvm, 2048, 2048/BN);
    gemm_f16<true><<<gm * (1024/BN), 256, DSMEM_BYTES>>>(
        (const __half*)m16, (const __half*)wmq, bmq, nullptr, qm, 1024, 1024/BN);
    gemm_f16<true><<<gm * (2048/BN), 256, DSMEM_BYTES>>>(
        (const __half*)l16, (const __half*)wlkv, blkv, nullptr, kvl, 2048, 2048/BN);

    // stage 2: per-token attention
    attn_kernel<<<NTOK, 256>>>();

    // stage 3: output projections + residual -> fp32 out
    gemm_f16<false><<<gm * (1024/BN), 256, DSMEM_BYTES>>>(
        (const __half*)al, (const __half*)wlo, blo, liquid, out_l, 1024, 1024/BN);
    gemm_f16<false><<<gm * (1024/BN), 256, DSMEM_BYTES>>>(
        (const __half*)am, (const __half*)wmo, bmo, mamba, out_m, 1024, 1024/BN);
}